// round 14
// baseline (speedup 1.0000x reference)
#include <cuda_runtime.h>
#include <cuda_bf16.h>
#include <cstdint>
#include <cstddef>

// ---------------- instance bounds (B=16, Lmax=1984, N=24064, D=512) ----------------
#define LMAX     2048
#define SEGMAX   16
#define BMAX     64
#define NTOK_MAX 32768
#define DFIX     512

// ---- device scratch. RULE: NEVER pass these symbols as kernel args from host code —
// ---- host-side shadow address is garbage (root cause of rounds 4/6/7/8/10).
__device__ float g_S[(size_t)SEGMAX * LMAX * LMAX];   // scores fp32; after softmax each
                                                      // row packs phi[L] | plo[L] bf16
__device__ __nv_bfloat16 g_zhi[(size_t)NTOK_MAX * DFIX];   // h split (row-major)
__device__ __nv_bfloat16 g_zlo[(size_t)NTOK_MAX * DFIX];
__device__ __nv_bfloat16 g_yhi[(size_t)NTOK_MAX * DFIX];   // x = hW^T+b split
__device__ __nv_bfloat16 g_ylo[(size_t)NTOK_MAX * DFIX];
__device__ __nv_bfloat16 g_zThi[(size_t)DFIX * NTOK_MAX];  // h^T split (d-major)
__device__ __nv_bfloat16 g_zTlo[(size_t)DFIX * NTOK_MAX];
__device__ __nv_bfloat16 g_whi[DFIX * DFIX];
__device__ __nv_bfloat16 g_wlo[DFIX * DFIX];
__device__ int g_len[BMAX];
__device__ int g_off[BMAX];

// ---------------- helpers ----------------
__device__ __forceinline__ uint32_t smem_u32(const void* p) {
    uint32_t a;
    asm("{ .reg .u64 t; cvta.to.shared.u64 t, %1; cvt.u32.u64 %0, t; }" : "=r"(a) : "l"(p));
    return a;
}
__device__ __forceinline__ void ldsm4(uint32_t* r, uint32_t addr) {
    asm volatile("ldmatrix.sync.aligned.m8n8.x4.shared.b16 {%0,%1,%2,%3}, [%4];"
                 : "=r"(r[0]), "=r"(r[1]), "=r"(r[2]), "=r"(r[3]) : "r"(addr));
}
__device__ __forceinline__ void mma16816(float* c, const uint32_t* a, const uint32_t* b) {
    asm volatile(
        "mma.sync.aligned.m16n8k16.row.col.f32.bf16.bf16.f32 "
        "{%0,%1,%2,%3}, {%4,%5,%6,%7}, {%8,%9}, {%0,%1,%2,%3};"
        : "+f"(c[0]), "+f"(c[1]), "+f"(c[2]), "+f"(c[3])
        : "r"(a[0]), "r"(a[1]), "r"(a[2]), "r"(a[3]), "r"(b[0]), "r"(b[1]));
}
__device__ __forceinline__ void split_f32(float v, __nv_bfloat16& hi, __nv_bfloat16& lo) {
    hi = __float2bfloat16(v);
    lo = __float2bfloat16(v - __bfloat162float(hi));
}

// smem: BK=16 slabs, row stride 24 bf16 (48 B, conflict-free ldmatrix row phases)
#define SKP 24
#define SLAB_ELEMS (128 * SKP)   // 3072 bf16 = 6144 B
#define SLAB_BYTES (SLAB_ELEMS * 2)

// ---------------- HMMA NT GEMM core: D[128,128] = A[128,K] * B[128,K]^T ------------
// ALL operands pre-split (hi, lo) bf16, sources inside our oversized statics.
// 128 threads = 4 warps (2m x 2n), warp tile 64x64 (halves cross-warp LDSM redundancy
// vs 64x32 — kernel is smem-BW-bound). K multiple of 16. Static 48KB smem, 2 CTAs/SM.
template <class Epi>
__device__ __forceinline__ void gemm_core(
    const __nv_bfloat16* __restrict__ Ahi, const __nv_bfloat16* __restrict__ Alo, int lda,
    const __nv_bfloat16* __restrict__ Bhi, const __nv_bfloat16* __restrict__ Blo, int ldb,
    int K, Epi epi)
{
    __shared__ __align__(16) __nv_bfloat16 sm[2][4][SLAB_ELEMS];  // 49152 B
    const int tid  = threadIdx.x;
    const int wid  = tid >> 5, lane = tid & 31;
    const int g    = lane >> 2, tg = lane & 3;
    const int wm   = (wid >> 1) * 64;
    const int wn   = (wid & 1) * 64;
    const int lrow = lane & 15, lhalf = (lane >> 4) * 8;

    float C[4][8][4];                       // 128 accum regs: mt x nt x 4
    #pragma unroll
    for (int i = 0; i < 4; i++)
        #pragma unroll
        for (int j = 0; j < 8; j++)
            #pragma unroll
            for (int k = 0; k < 4; k++) C[i][j][k] = 0.f;

    uint4 rah[2], ral[2], rbh[2], rbl[2];   // staging: row = tid, 2 x 16B chunks/row

    auto load_slab = [&](int s) {
        const int k0 = s << 4;
        #pragma unroll
        for (int c = 0; c < 2; c++) {
            rah[c] = *(const uint4*)(Ahi + (size_t)tid * lda + k0 + c * 8);
            ral[c] = *(const uint4*)(Alo + (size_t)tid * lda + k0 + c * 8);
            rbh[c] = *(const uint4*)(Bhi + (size_t)tid * ldb + k0 + c * 8);
            rbl[c] = *(const uint4*)(Blo + (size_t)tid * ldb + k0 + c * 8);
        }
    };
    auto store_slab = [&](int buf) {
        #pragma unroll
        for (int c = 0; c < 2; c++) {
            int e = tid * SKP + c * 8;
            *(uint4*)(&sm[buf][0][e]) = rah[c];
            *(uint4*)(&sm[buf][1][e]) = ral[c];
            *(uint4*)(&sm[buf][2][e]) = rbh[c];
            *(uint4*)(&sm[buf][3][e]) = rbl[c];
        }
    };

    const int slabs = K >> 4;
    load_slab(0);
    store_slab(0);
    __syncthreads();

    for (int s = 0; s < slabs; s++) {
        const bool more = (s + 1 < slabs);
        if (more) load_slab(s + 1);                 // global loads overlap compute

        const uint32_t sbase = smem_u32(&sm[s & 1][0][0]);
        uint32_t ah[4][4], al[4][4];
        #pragma unroll
        for (int mt = 0; mt < 4; mt++) {
            uint32_t off = (uint32_t)((wm + mt * 16 + lrow) * SKP + lhalf) * 2u;
            ldsm4(ah[mt], sbase + off);
            ldsm4(al[mt], sbase + SLAB_BYTES + off);
        }
        #pragma unroll
        for (int nh = 0; nh < 2; nh++) {            // two 32-wide n halves: 16 b-frag regs
            uint32_t bh[2][4], bl[2][4];
            #pragma unroll
            for (int j = 0; j < 2; j++) {
                uint32_t off = (uint32_t)((wn + nh * 32 + j * 16 + lrow) * SKP + lhalf) * 2u;
                ldsm4(bh[j], sbase + 2 * SLAB_BYTES + off);
                ldsm4(bl[j], sbase + 3 * SLAB_BYTES + off);
            }
            #pragma unroll
            for (int pass = 0; pass < 3; pass++)
                #pragma unroll
                for (int mt = 0; mt < 4; mt++)
                    #pragma unroll
                    for (int q = 0; q < 4; q++) {
                        int j = q >> 1, lo = q & 1;
                        uint32_t bv[2];
                        if (pass == 1) { bv[0] = bl[j][lo]; bv[1] = bl[j][lo + 2]; }
                        else           { bv[0] = bh[j][lo]; bv[1] = bh[j][lo + 2]; }
                        mma16816(C[mt][nh * 4 + q], (pass == 2) ? al[mt] : ah[mt], bv);
                    }
        }

        if (more) store_slab((s + 1) & 1);          // other buffer: safe w/o pre-sync
        __syncthreads();
    }

    #pragma unroll
    for (int mt = 0; mt < 4; mt++)
        #pragma unroll
        for (int nt = 0; nt < 8; nt++)
            epi(wm + mt * 16 + g, wn + nt * 8 + 2 * tg, C[mt][nt]);
}

// ---------------- offsets (int32/int64 lengths) ----------------
__global__ void offsets_kernel(const int* __restrict__ lens_raw, int count, int ntok) {
    if (threadIdx.x != 0 || blockIdx.x != 0) return;
    bool is64 = (count >= 2) && (lens_raw[1] == 0) && (lens_raw[0] != 0);
    int acc = 0;
    for (int i = 0; i < BMAX; i++) {
        int L = 0;
        if (i < count && acc < ntok) L = lens_raw[is64 ? 2 * i : i];
        if (L < 0) L = 0;
        if (L > LMAX) L = LMAX;
        g_len[i] = L; g_off[i] = acc; acc += L;
    }
}

// ---------------- split W (device symbols referenced IN kernel only) ----------------
__global__ void split_w(const float* __restrict__ src) {
    int i = (blockIdx.x * 256 + threadIdx.x) * 2;   // grid covers exactly DFIX*DFIX
    float2 v = *(const float2*)(src + i);
    __nv_bfloat16 h0, l0, h1, l1;
    split_f32(v.x, h0, l0); split_f32(v.y, h1, l1);
    *(__nv_bfloat162*)(g_whi + i) = __halves2bfloat162(h0, h1);
    *(__nv_bfloat162*)(g_wlo + i) = __halves2bfloat162(l0, l1);
}

// ---------------- split h row-major -> g_zhi/g_zlo ----------------
__global__ void split_z(const float* __restrict__ src, int n) {
    int i = (blockIdx.x * 256 + threadIdx.x) * 2;
    if (i >= n) return;
    float2 v = *(const float2*)(src + i);
    __nv_bfloat16 h0, l0, h1, l1;
    split_f32(v.x, h0, l0); split_f32(v.y, h1, l1);
    *(__nv_bfloat162*)(g_zhi + i) = __halves2bfloat162(h0, h1);
    *(__nv_bfloat162*)(g_zlo + i) = __halves2bfloat162(l0, l1);
}

// ---------------- transpose + split: h[N,512] -> zT[512, NTOK_MAX] ----------------
__global__ void transpose_split(const float* __restrict__ h, int Ntok) {
    __shared__ float t[32][33];
    int d0 = blockIdx.x * 32, n0 = blockIdx.y * 32;
    for (int i = threadIdx.y; i < 32; i += 8) {
        int n = n0 + i;
        t[i][threadIdx.x] = (n < Ntok) ? h[(size_t)n * DFIX + d0 + threadIdx.x] : 0.f;
    }
    __syncthreads();
    for (int i = threadIdx.y; i < 32; i += 8) {
        int d = d0 + i, n = n0 + threadIdx.x;
        if (n >= NTOK_MAX) continue;
        float v = t[threadIdx.x][i];
        __nv_bfloat16 hi, lo; split_f32(v, hi, lo);
        g_zThi[(size_t)d * NTOK_MAX + n] = hi;
        g_zTlo[(size_t)d * NTOK_MAX + n] = lo;
    }
}

// ---------------- GEMM 1: x = z W^T + b -> yhi/ylo ----------------
__global__ __launch_bounds__(128, 2)
void linear_gemm(const float* __restrict__ bias, int Ntok)
{
    int col0 = blockIdx.x * 128, row0 = blockIdx.y * 128;
    if (row0 >= Ntok) return;
    auto epi = [&](int gm, int gn, const float* c) {
        int gcol = col0 + gn;
        float b0 = bias[gcol], b1 = bias[gcol + 1];
        #pragma unroll
        for (int half = 0; half < 2; half++) {
            int grow = row0 + gm + half * 8;
            if (grow >= Ntok) continue;
            float f0 = c[half * 2] + b0, f1 = c[half * 2 + 1] + b1;
            __nv_bfloat16 h0, l0, h1, l1;
            split_f32(f0, h0, l0); split_f32(f1, h1, l1);
            size_t base = (size_t)grow * DFIX + gcol;
            *(__nv_bfloat162*)(g_yhi + base) = __halves2bfloat162(h0, h1);
            *(__nv_bfloat162*)(g_ylo + base) = __halves2bfloat162(l0, l1);
        }
    };
    gemm_core(g_zhi + (size_t)row0 * DFIX, g_zlo + (size_t)row0 * DFIX, DFIX,
              g_whi + (size_t)col0 * DFIX, g_wlo + (size_t)col0 * DFIX, DFIX,
              DFIX, epi);
}

// ---------------- GEMM 2: S = Z Y^T per segment ----------------
__global__ __launch_bounds__(128, 2)
void scores_gemm()
{
    int b = blockIdx.z;
    int L = g_len[b];
    int col0 = blockIdx.x * 128, row0 = blockIdx.y * 128;
    if (L == 0 || row0 >= L || col0 >= L) return;
    int off = g_off[b];
    int Mv = L - row0; if (Mv > 128) Mv = 128;
    int Nv = L - col0; if (Nv > 128) Nv = 128;
    float* S = g_S + (size_t)b * LMAX * LMAX;
    auto epi = [&](int gm, int gn, const float* c) {
        if (gn >= Nv) return;
        #pragma unroll
        for (int half = 0; half < 2; half++) {
            int rm = gm + half * 8;
            if (rm >= Mv) continue;
            *(float2*)(S + (size_t)(row0 + rm) * LMAX + col0 + gn) =
                make_float2(c[half * 2], c[half * 2 + 1]);
        }
    };
    gemm_core(g_zhi + (size_t)(off + row0) * DFIX, g_zlo + (size_t)(off + row0) * DFIX, DFIX,
              g_yhi + (size_t)(off + col0) * DFIX, g_ylo + (size_t)(off + col0) * DFIX, DFIX,
              DFIX, epi);
}

// ---------------- softmax: fp32 row in, packed (phi[L] | plo[L]) bf16 out in place --
__global__ void softmax_kernel()
{
    int b = blockIdx.y, l = blockIdx.x;
    int L = g_len[b];
    if (l >= L) return;
    float* row = g_S + (size_t)b * LMAX * LMAX + (size_t)l * LMAX;
    __nv_bfloat16* phi = (__nv_bfloat16*)row;
    __nv_bfloat16* plo = phi + L;
    int tid = threadIdx.x;

    float v[LMAX / 256];
    float mx = -1e30f;
    #pragma unroll
    for (int i = 0; i < LMAX / 256; i++) {
        int m = tid + i * 256;
        v[i] = (m < L) ? row[m] : -1e30f;
        mx = fmaxf(mx, v[i]);
    }
    __shared__ float red[256];
    red[tid] = mx; __syncthreads();
    #pragma unroll
    for (int s = 128; s > 0; s >>= 1) {
        if (tid < s) red[tid] = fmaxf(red[tid], red[tid + s]);
        __syncthreads();
    }
    mx = red[0]; __syncthreads();

    float sum = 0.f;
    #pragma unroll
    for (int i = 0; i < LMAX / 256; i++) {
        int m = tid + i * 256;
        v[i] = (m < L) ? __expf(v[i] - mx) : 0.f;
        sum += v[i];
    }
    red[tid] = sum; __syncthreads();
    #pragma unroll
    for (int s = 128; s > 0; s >>= 1) {
        if (tid < s) red[tid] += red[tid + s];
        __syncthreads();
    }
    float inv = 1.f / red[0];
    __syncthreads();   // all fp32 reads of this row precede the in-place overwrite

    #pragma unroll
    for (int i = 0; i < LMAX / 256; i++) {
        int m = tid + i * 256;
        if (m < L) {
            float p = v[i] * inv;
            __nv_bfloat16 hi, lo; split_f32(p, hi, lo);
            phi[m] = hi; plo[m] = lo;
        }
    }
}

// ---------------- GEMM 3: out = P Z  (A = packed probs, B = zT) ----------------
__global__ __launch_bounds__(128, 2)
void out_gemm(float* __restrict__ out)
{
    int b = blockIdx.z;
    int L = g_len[b];
    int col0 = blockIdx.x * 128, row0 = blockIdx.y * 128;
    if (L == 0 || row0 >= L) return;
    int off = g_off[b];
    int Mv = L - row0; if (Mv > 128) Mv = 128;
    const __nv_bfloat16* base =
        (const __nv_bfloat16*)(g_S + (size_t)b * LMAX * LMAX) + (size_t)row0 * 2 * LMAX;
    auto epi = [&](int gm, int gn, const float* c) {
        #pragma unroll
        for (int half = 0; half < 2; half++) {
            int rm = gm + half * 8;
            if (rm >= Mv) continue;
            *(float2*)(out + (size_t)(off + row0 + rm) * DFIX + col0 + gn) =
                make_float2(c[half * 2], c[half * 2 + 1]);
        }
    };
    gemm_core(base, base + L, 2 * LMAX,
              g_zThi + (size_t)col0 * NTOK_MAX + off,
              g_zTlo + (size_t)col0 * NTOK_MAX + off, NTOK_MAX,
              L /* K: multiple of 64 */, epi);
}

// ---------------- launch (NO device symbols passed as args — host shadows!) --------
extern "C" void kernel_launch(void* const* d_in, const int* in_sizes, int n_in,
                              void* d_out, int out_size)
{
    const float* h    = (const float*)d_in[0];
    const float* W    = (const float*)d_in[1];
    const float* bias = (const float*)d_in[2];
    const int*   lens = (const int*)d_in[3];

    int D    = in_sizes[2];
    int Ntok = in_sizes[0] / D;
    int B    = in_sizes[3];
    if (B > BMAX) B = BMAX;
    int Bz = B < SEGMAX ? B : SEGMAX;

    offsets_kernel<<<1, 32>>>(lens, B, Ntok);

    split_w<<<DFIX * DFIX / 512, 256>>>(W);
    int nz = Ntok * DFIX;
    split_z<<<(nz / 2 + 255) / 256, 256>>>(h, nz);
    transpose_split<<<dim3(DFIX / 32, (Ntok + 31) / 32), dim3(32, 8)>>>(h, Ntok);

    int rowTiles = (Ntok + 127) / 128;
    linear_gemm<<<dim3(DFIX / 128, rowTiles), 128>>>(bias, Ntok);

    scores_gemm<<<dim3(LMAX / 128, LMAX / 128, Bz), 128>>>();

    softmax_kernel<<<dim3(LMAX, Bz), 256>>>();

    out_gemm<<<dim3(DFIX / 128, LMAX / 128, Bz), 128>>>((float*)d_out);
}

// round 15
// speedup vs baseline: 1.2247x; 1.2247x over previous
#include <cuda_runtime.h>
#include <cuda_bf16.h>
#include <cuda_fp16.h>
#include <cstdint>
#include <cstddef>

// ---------------- instance bounds (B=16, Lmax=1984, N=24064, D=512) ----------------
#define LMAX     2048
#define SEGMAX   16
#define BMAX     64
#define NTOK_MAX 32768
#define DFIX     512

// ---- device scratch (384 MiB). RULE: NEVER pass these symbols as kernel args from
// ---- host code — host-side shadow address is garbage (rounds 4/6/7/8/10).
__device__ float g_S[(size_t)SEGMAX * LMAX * LMAX];   // scores fp32; after softmax each
                                                      // row starts with P[L] fp16
__device__ float g_x[(size_t)NTOK_MAX * DFIX];        // x = h W^T + b
__device__ __half g_zThi[(size_t)DFIX * NTOK_MAX];    // h^T fp16 split (d-major)
__device__ __half g_zTlo[(size_t)DFIX * NTOK_MAX];
__device__ int g_len[BMAX];
__device__ int g_off[BMAX];

// ---------------- helpers ----------------
__device__ __forceinline__ uint32_t smem_u32(const void* p) {
    uint32_t a;
    asm("{ .reg .u64 t; cvta.to.shared.u64 t, %1; cvt.u32.u64 %0, t; }" : "=r"(a) : "l"(p));
    return a;
}
__device__ __forceinline__ void ldsm4(uint32_t* r, uint32_t addr) {
    asm volatile("ldmatrix.sync.aligned.m8n8.x4.shared.b16 {%0,%1,%2,%3}, [%4];"
                 : "=r"(r[0]), "=r"(r[1]), "=r"(r[2]), "=r"(r[3]) : "r"(addr));
}
__device__ __forceinline__ void mma16816(float* c, const uint32_t* a, const uint32_t* b) {
    asm volatile(
        "mma.sync.aligned.m16n8k16.row.col.f32.bf16.bf16.f32 "
        "{%0,%1,%2,%3}, {%4,%5,%6,%7}, {%8,%9}, {%0,%1,%2,%3};"
        : "+f"(c[0]), "+f"(c[1]), "+f"(c[2]), "+f"(c[3])
        : "r"(a[0]), "r"(a[1]), "r"(a[2]), "r"(a[3]), "r"(b[0]), "r"(b[1]));
}
__device__ __forceinline__ void mma16816h(float* c, const uint32_t* a, const uint32_t* b) {
    asm volatile(
        "mma.sync.aligned.m16n8k16.row.col.f32.f16.f16.f32 "
        "{%0,%1,%2,%3}, {%4,%5,%6,%7}, {%8,%9}, {%0,%1,%2,%3};"
        : "+f"(c[0]), "+f"(c[1]), "+f"(c[2]), "+f"(c[3])
        : "r"(a[0]), "r"(a[1]), "r"(a[2]), "r"(a[3]), "r"(b[0]), "r"(b[1]));
}
__device__ __forceinline__ void split_f32(float v, __nv_bfloat16& hi, __nv_bfloat16& lo) {
    hi = __float2bfloat16(v);
    lo = __float2bfloat16(v - __bfloat162float(hi));
}
__device__ __forceinline__ void split_f32h(float v, __half& hi, __half& lo) {
    hi = __float2half(v);
    lo = __float2half(v - __half2float(hi));
}

// smem: BK=16 slabs, row stride 24 elems (48 B, conflict-free ldmatrix row phases)
#define SKP 24
#define SLAB_ELEMS (128 * SKP)   // 3072 elems = 6144 B
#define SLAB_BYTES (SLAB_ELEMS * 2)

// ---------------- bf16 3-pass NT GEMM core (EXACTLY the R9/R13-proven kernel) -------
// A fp32 (split on the fly). B either fp32 or pre-split bf16 (BPRE).
// 256 threads = 8 warps (2m x 4n), 64x32 per warp, K multiple of 16.
template <bool BPRE, class Epi>
__device__ __forceinline__ void gemm_core(
    const float* __restrict__ Af, int lda, int Mv,
    const float* __restrict__ Bf,
    const __nv_bfloat16* __restrict__ Bhi, const __nv_bfloat16* __restrict__ Blo,
    int ldb, int Nv, int K, Epi epi)
{
    __shared__ __align__(16) __nv_bfloat16 sm[2][4][SLAB_ELEMS];  // 49152 B
    const int tid  = threadIdx.x;
    const int wid  = tid >> 5, lane = tid & 31;
    const int g    = lane >> 2, tg = lane & 3;
    const int wm   = (wid >> 2) * 64;
    const int wn   = (wid & 3) * 32;
    const int lrow = lane & 15, lhalf = (lane >> 4) * 8;

    float C[4][4][4];
    #pragma unroll
    for (int i = 0; i < 4; i++)
        #pragma unroll
        for (int j = 0; j < 4; j++)
            #pragma unroll
            for (int k = 0; k < 4; k++) C[i][j][k] = 0.f;

    float4 ra[2], rbf[2];
    uint4  rbh, rbl;

    auto load_slab = [&](int s) {
        const int k0 = s << 4;
        #pragma unroll
        for (int it = 0; it < 2; it++) {
            int idx = tid + it * 256;
            int r = idx >> 2, q = idx & 3;
            ra[it] = (r < Mv) ? *(const float4*)(Af + (size_t)r * lda + k0 + q * 4)
                              : make_float4(0.f, 0.f, 0.f, 0.f);
        }
        if (!BPRE) {
            #pragma unroll
            for (int it = 0; it < 2; it++) {
                int idx = tid + it * 256;
                int r = idx >> 2, q = idx & 3;
                rbf[it] = (r < Nv) ? *(const float4*)(Bf + (size_t)r * ldb + k0 + q * 4)
                                   : make_float4(0.f, 0.f, 0.f, 0.f);
            }
        } else {
            int r = tid >> 1, q = tid & 1;
            if (r < Nv) {
                rbh = *(const uint4*)(Bhi + (size_t)r * ldb + k0 + q * 8);
                rbl = *(const uint4*)(Blo + (size_t)r * ldb + k0 + q * 8);
            } else {
                rbh = make_uint4(0u, 0u, 0u, 0u); rbl = rbh;
            }
        }
    };

    auto store_f4 = [&](__nv_bfloat16* hi, __nv_bfloat16* lo, int r, int q, float4 v) {
        __nv_bfloat16 h0, l0, h1, l1, h2, l2, h3, l3;
        split_f32(v.x, h0, l0); split_f32(v.y, h1, l1);
        split_f32(v.z, h2, l2); split_f32(v.w, h3, l3);
        int e = r * SKP + q * 4;
        *(__nv_bfloat162*)(hi + e)     = __halves2bfloat162(h0, h1);
        *(__nv_bfloat162*)(hi + e + 2) = __halves2bfloat162(h2, h3);
        *(__nv_bfloat162*)(lo + e)     = __halves2bfloat162(l0, l1);
        *(__nv_bfloat162*)(lo + e + 2) = __halves2bfloat162(l2, l3);
    };

    auto store_slab = [&](int buf) {
        #pragma unroll
        for (int it = 0; it < 2; it++) {
            int idx = tid + it * 256;
            store_f4(sm[buf][0], sm[buf][1], idx >> 2, idx & 3, ra[it]);
        }
        if (!BPRE) {
            #pragma unroll
            for (int it = 0; it < 2; it++) {
                int idx = tid + it * 256;
                store_f4(sm[buf][2], sm[buf][3], idx >> 2, idx & 3, rbf[it]);
            }
        } else {
            int r = tid >> 1, q = tid & 1;
            *(uint4*)(&sm[buf][2][r * SKP + q * 8]) = rbh;
            *(uint4*)(&sm[buf][3][r * SKP + q * 8]) = rbl;
        }
    };

    const int slabs = K >> 4;
    load_slab(0);
    store_slab(0);
    __syncthreads();

    for (int s = 0; s < slabs; s++) {
        const bool more = (s + 1 < slabs);
        if (more) load_slab(s + 1);

        const uint32_t sbase = smem_u32(&sm[s & 1][0][0]);
        uint32_t ah[4][4], al[4][4], bfr[2][4], blr[2][4];
        #pragma unroll
        for (int mt = 0; mt < 4; mt++) {
            uint32_t off = (uint32_t)((wm + mt * 16 + lrow) * SKP + lhalf) * 2u;
            ldsm4(ah[mt], sbase + off);
            ldsm4(al[mt], sbase + SLAB_BYTES + off);
        }
        #pragma unroll
        for (int np = 0; np < 2; np++) {
            uint32_t off = (uint32_t)((wn + np * 16 + lrow) * SKP + lhalf) * 2u;
            ldsm4(bfr[np], sbase + 2 * SLAB_BYTES + off);
            ldsm4(blr[np], sbase + 3 * SLAB_BYTES + off);
        }
        #pragma unroll
        for (int mt = 0; mt < 4; mt++)
            #pragma unroll
            for (int nt = 0; nt < 4; nt++) {
                int np = nt >> 1, lo = nt & 1;
                uint32_t bh[2] = { bfr[np][lo], bfr[np][lo + 2] };
                uint32_t bl[2] = { blr[np][lo], blr[np][lo + 2] };
                mma16816(C[mt][nt], ah[mt], bh);   // hi*hi
                mma16816(C[mt][nt], ah[mt], bl);   // hi*lo
                mma16816(C[mt][nt], al[mt], bh);   // lo*hi
            }

        if (more) store_slab((s + 1) & 1);
        __syncthreads();
    }

    #pragma unroll
    for (int mt = 0; mt < 4; mt++)
        #pragma unroll
        for (int nt = 0; nt < 4; nt++)
            epi(wm + mt * 16 + g, wn + nt * 8 + 2 * tg, C[mt][nt]);
}

// ---------------- fp16 2-pass NT GEMM core for out = P Z ---------------------------
// A = plain fp16 P [128 x K] (lda elems). B = fp16 (hi, lo) pair. Same 8-warp layout.
template <class Epi>
__device__ __forceinline__ void gemm_core_pz(
    const __half* __restrict__ A, int lda,
    const __half* __restrict__ Bhi, const __half* __restrict__ Blo, int ldb,
    int K, Epi epi)
{
    __shared__ __align__(16) __half sm2[2][3][SLAB_ELEMS];   // 36864 B
    const int tid  = threadIdx.x;
    const int wid  = tid >> 5, lane = tid & 31;
    const int g    = lane >> 2, tg = lane & 3;
    const int wm   = (wid >> 2) * 64;
    const int wn   = (wid & 3) * 32;
    const int lrow = lane & 15, lhalf = (lane >> 4) * 8;
    const int cr   = tid >> 1, cq = tid & 1;

    float C[4][4][4];
    #pragma unroll
    for (int i = 0; i < 4; i++)
        #pragma unroll
        for (int j = 0; j < 4; j++)
            #pragma unroll
            for (int k = 0; k < 4; k++) C[i][j][k] = 0.f;

    uint4 rA, rbh, rbl;
    auto load_slab = [&](int s) {
        const int k0 = s << 4;
        rA  = *(const uint4*)(A   + (size_t)cr * lda + k0 + cq * 8);
        rbh = *(const uint4*)(Bhi + (size_t)cr * ldb + k0 + cq * 8);
        rbl = *(const uint4*)(Blo + (size_t)cr * ldb + k0 + cq * 8);
    };
    auto store_slab = [&](int buf) {
        int e = cr * SKP + cq * 8;
        *(uint4*)(&sm2[buf][0][e]) = rA;
        *(uint4*)(&sm2[buf][1][e]) = rbh;
        *(uint4*)(&sm2[buf][2][e]) = rbl;
    };

    const int slabs = K >> 4;
    load_slab(0);
    store_slab(0);
    __syncthreads();

    for (int s = 0; s < slabs; s++) {
        const bool more = (s + 1 < slabs);
        if (more) load_slab(s + 1);

        const uint32_t sbase = smem_u32(&sm2[s & 1][0][0]);
        uint32_t ah[4][4], bfr[2][4], blr[2][4];
        #pragma unroll
        for (int mt = 0; mt < 4; mt++) {
            uint32_t off = (uint32_t)((wm + mt * 16 + lrow) * SKP + lhalf) * 2u;
            ldsm4(ah[mt], sbase + off);
        }
        #pragma unroll
        for (int np = 0; np < 2; np++) {
            uint32_t off = (uint32_t)((wn + np * 16 + lrow) * SKP + lhalf) * 2u;
            ldsm4(bfr[np], sbase + (uint32_t)SLAB_BYTES + off);
            ldsm4(blr[np], sbase + 2u * SLAB_BYTES + off);
        }
        #pragma unroll
        for (int mt = 0; mt < 4; mt++)
            #pragma unroll
            for (int nt = 0; nt < 4; nt++) {
                int np = nt >> 1, lo = nt & 1;
                uint32_t bh[2] = { bfr[np][lo], bfr[np][lo + 2] };
                uint32_t bl[2] = { blr[np][lo], blr[np][lo + 2] };
                mma16816h(C[mt][nt], ah[mt], bh);   // P * Z_hi
                mma16816h(C[mt][nt], ah[mt], bl);   // P * Z_lo
            }

        if (more) store_slab((s + 1) & 1);
        __syncthreads();
    }

    #pragma unroll
    for (int mt = 0; mt < 4; mt++)
        #pragma unroll
        for (int nt = 0; nt < 4; nt++)
            epi(wm + mt * 16 + g, wn + nt * 8 + 2 * tg, C[mt][nt]);
}

// ---------------- offsets (int32/int64 lengths) ----------------
__global__ void offsets_kernel(const int* __restrict__ lens_raw, int count, int ntok) {
    if (threadIdx.x != 0 || blockIdx.x != 0) return;
    bool is64 = (count >= 2) && (lens_raw[1] == 0) && (lens_raw[0] != 0);
    int acc = 0;
    for (int i = 0; i < BMAX; i++) {
        int L = 0;
        if (i < count && acc < ntok) L = lens_raw[is64 ? 2 * i : i];
        if (L < 0) L = 0;
        if (L > LMAX) L = LMAX;
        g_len[i] = L; g_off[i] = acc; acc += L;
    }
}

// ---------------- transpose + fp16 split: h[N,512] -> zT[512, NTOK_MAX] -------------
__global__ void transpose_split(const float* __restrict__ h, int Ntok) {
    __shared__ float t[32][33];
    int d0 = blockIdx.x * 32, n0 = blockIdx.y * 32;
    for (int i = threadIdx.y; i < 32; i += 8) {
        int n = n0 + i;
        t[i][threadIdx.x] = (n < Ntok) ? h[(size_t)n * DFIX + d0 + threadIdx.x] : 0.f;
    }
    __syncthreads();
    for (int i = threadIdx.y; i < 32; i += 8) {
        int d = d0 + i, n = n0 + threadIdx.x;
        if (n >= NTOK_MAX) continue;
        float v = t[threadIdx.x][i];
        __half hi, lo; split_f32h(v, hi, lo);
        g_zThi[(size_t)d * NTOK_MAX + n] = hi;
        g_zTlo[(size_t)d * NTOK_MAX + n] = lo;
    }
}

// ---------------- GEMM 1: x = h W^T + b ----------------
__global__ __launch_bounds__(256)
void linear_gemm(const float* __restrict__ h, const float* __restrict__ W,
                 const float* __restrict__ bias, int Ntok)
{
    int col0 = blockIdx.x * 128, row0 = blockIdx.y * 128;
    if (row0 >= Ntok) return;
    int Mv = Ntok - row0; if (Mv > 128) Mv = 128;
    auto epi = [&](int gm, int gn, const float* c) {
        int gcol = col0 + gn;
        float b0 = bias[gcol], b1 = bias[gcol + 1];
        #pragma unroll
        for (int half = 0; half < 2; half++) {
            int grow = row0 + gm + half * 8;
            if (grow >= Ntok) continue;
            *(float2*)(g_x + (size_t)grow * DFIX + gcol) =
                make_float2(c[half * 2] + b0, c[half * 2 + 1] + b1);
        }
    };
    gemm_core<false>(h + (size_t)row0 * DFIX, DFIX, Mv,
                     W + (size_t)col0 * DFIX, nullptr, nullptr, DFIX, 128,
                     DFIX, epi);
}

// ---------------- GEMM 2: S = Z Y^T per segment ----------------
__global__ __launch_bounds__(256)
void scores_gemm(const float* __restrict__ h)
{
    int b = blockIdx.z;
    int L = g_len[b];
    int col0 = blockIdx.x * 128, row0 = blockIdx.y * 128;
    if (L == 0 || row0 >= L || col0 >= L) return;
    int off = g_off[b];
    int Mv = L - row0; if (Mv > 128) Mv = 128;
    int Nv = L - col0; if (Nv > 128) Nv = 128;
    float* S = g_S + (size_t)b * LMAX * LMAX;
    auto epi = [&](int gm, int gn, const float* c) {
        if (gn >= Nv) return;
        #pragma unroll
        for (int half = 0; half < 2; half++) {
            int rm = gm + half * 8;
            if (rm >= Mv) continue;
            *(float2*)(S + (size_t)(row0 + rm) * LMAX + col0 + gn) =
                make_float2(c[half * 2], c[half * 2 + 1]);
        }
    };
    gemm_core<false>(h + (size_t)(off + row0) * DFIX, DFIX, Mv,
                     g_x + (size_t)(off + col0) * DFIX, nullptr, nullptr, DFIX, Nv,
                     DFIX, epi);
}

// ---------------- softmax: fp32 row in, fp16 P[L] out in place at row start --------
__global__ void softmax_kernel()
{
    int b = blockIdx.y, l = blockIdx.x;
    int L = g_len[b];
    if (l >= L) return;
    float* row = g_S + (size_t)b * LMAX * LMAX + (size_t)l * LMAX;
    __half* P = (__half*)row;
    int tid = threadIdx.x;

    float v[LMAX / 256];
    float mx = -1e30f;
    #pragma unroll
    for (int i = 0; i < LMAX / 256; i++) {
        int m = tid + i * 256;
        v[i] = (m < L) ? row[m] : -1e30f;
        mx = fmaxf(mx, v[i]);
    }
    __shared__ float red[256];
    red[tid] = mx; __syncthreads();
    #pragma unroll
    for (int s = 128; s > 0; s >>= 1) {
        if (tid < s) red[tid] = fmaxf(red[tid], red[tid + s]);
        __syncthreads();
    }
    mx = red[0]; __syncthreads();

    float sum = 0.f;
    #pragma unroll
    for (int i = 0; i < LMAX / 256; i++) {
        int m = tid + i * 256;
        v[i] = (m < L) ? __expf(v[i] - mx) : 0.f;
        sum += v[i];
    }
    red[tid] = sum; __syncthreads();
    #pragma unroll
    for (int s = 128; s > 0; s >>= 1) {
        if (tid < s) red[tid] += red[tid + s];
        __syncthreads();
    }
    float inv = 1.f / red[0];
    __syncthreads();   // all fp32 reads of this row precede the in-place overwrite

    #pragma unroll
    for (int i = 0; i < LMAX / 256; i++) {
        int m = tid + i * 256;
        if (m < L) P[m] = __float2half(v[i] * inv);
    }
}

// ---------------- GEMM 3: out = P Z  (fp16 2-pass core) ----------------
__global__ __launch_bounds__(256)
void out_gemm(float* __restrict__ out)
{
    int b = blockIdx.z;
    int L = g_len[b];
    int col0 = blockIdx.x * 128, row0 = blockIdx.y * 128;
    if (L == 0 || row0 >= L) return;
    int off = g_off[b];
    int Mv = L - row0; if (Mv > 128) Mv = 128;
    const __half* P = (const __half*)(g_S + (size_t)b * LMAX * LMAX)
                      + (size_t)row0 * 2 * LMAX;   // row stride 2*LMAX halves
    auto epi = [&](int gm, int gn, const float* c) {
        #pragma unroll
        for (int half = 0; half < 2; half++) {
            int rm = gm + half * 8;
            if (rm >= Mv) continue;
            *(float2*)(out + (size_t)(off + row0 + rm) * DFIX + col0 + gn) =
                make_float2(c[half * 2], c[half * 2 + 1]);
        }
    };
    gemm_core_pz(P, 2 * LMAX,
                 g_zThi + (size_t)col0 * NTOK_MAX + off,
                 g_zTlo + (size_t)col0 * NTOK_MAX + off, NTOK_MAX,
                 L /* K: multiple of 64 */, epi);
}

// ---------------- launch (NO device symbols passed as args — host shadows!) --------
extern "C" void kernel_launch(void* const* d_in, const int* in_sizes, int n_in,
                              void* d_out, int out_size)
{
    const float* h    = (const float*)d_in[0];
    const float* W    = (const float*)d_in[1];
    const float* bias = (const float*)d_in[2];
    const int*   lens = (const int*)d_in[3];

    int D    = in_sizes[2];
    int Ntok = in_sizes[0] / D;
    int B    = in_sizes[3];
    if (B > BMAX) B = BMAX;
    int Bz = B < SEGMAX ? B : SEGMAX;

    offsets_kernel<<<1, 32>>>(lens, B, Ntok);

    transpose_split<<<dim3(DFIX / 32, (Ntok + 31) / 32), dim3(32, 8)>>>(h, Ntok);

    int rowTiles = (Ntok + 127) / 128;
    linear_gemm<<<dim3(DFIX / 128, rowTiles), 256>>>(h, W, bias, Ntok);

    scores_gemm<<<dim3(LMAX / 128, LMAX / 128, Bz), 256>>>(h);

    softmax_kernel<<<dim3(LMAX, Bz), 256>>>();

    out_gemm<<<dim3(DFIX / 128, LMAX / 128, Bz), 256>>>((float*)d_out);
}

// round 16
// speedup vs baseline: 1.3945x; 1.1386x over previous
#include <cuda_runtime.h>
#include <cuda_bf16.h>
#include <cuda_fp16.h>
#include <cstdint>
#include <cstddef>

// ---------------- instance bounds (B=16, Lmax=1984, N=24064, D=512) ----------------
#define LMAX     2048
#define SEGMAX   16
#define BMAX     64
#define NTOK_MAX 32768
#define DFIX     512

// ---- device scratch (384 MiB). RULE: NEVER pass these symbols as kernel args from
// ---- host code — host-side shadow address is garbage (rounds 4/6/7/8/10).
__device__ float g_S[(size_t)SEGMAX * LMAX * LMAX];   // scores fp32; after softmax each
                                                      // row starts with P[L] fp16
__device__ float g_x[(size_t)NTOK_MAX * DFIX];        // x = h W^T + b
__device__ __half g_zThi[(size_t)DFIX * NTOK_MAX];    // h^T fp16 split (d-major)
__device__ __half g_zTlo[(size_t)DFIX * NTOK_MAX];
__device__ int g_len[BMAX];
__device__ int g_off[BMAX];

// ---------------- helpers ----------------
__device__ __forceinline__ uint32_t smem_u32(const void* p) {
    uint32_t a;
    asm("{ .reg .u64 t; cvta.to.shared.u64 t, %1; cvt.u32.u64 %0, t; }" : "=r"(a) : "l"(p));
    return a;
}
__device__ __forceinline__ void ldsm4(uint32_t* r, uint32_t addr) {
    asm volatile("ldmatrix.sync.aligned.m8n8.x4.shared.b16 {%0,%1,%2,%3}, [%4];"
                 : "=r"(r[0]), "=r"(r[1]), "=r"(r[2]), "=r"(r[3]) : "r"(addr));
}
__device__ __forceinline__ void mma16816(float* c, const uint32_t* a, const uint32_t* b) {
    asm volatile(
        "mma.sync.aligned.m16n8k16.row.col.f32.bf16.bf16.f32 "
        "{%0,%1,%2,%3}, {%4,%5,%6,%7}, {%8,%9}, {%0,%1,%2,%3};"
        : "+f"(c[0]), "+f"(c[1]), "+f"(c[2]), "+f"(c[3])
        : "r"(a[0]), "r"(a[1]), "r"(a[2]), "r"(a[3]), "r"(b[0]), "r"(b[1]));
}
__device__ __forceinline__ void mma16816h(float* c, const uint32_t* a, const uint32_t* b) {
    asm volatile(
        "mma.sync.aligned.m16n8k16.row.col.f32.f16.f16.f32 "
        "{%0,%1,%2,%3}, {%4,%5,%6,%7}, {%8,%9}, {%0,%1,%2,%3};"
        : "+f"(c[0]), "+f"(c[1]), "+f"(c[2]), "+f"(c[3])
        : "r"(a[0]), "r"(a[1]), "r"(a[2]), "r"(a[3]), "r"(b[0]), "r"(b[1]));
}
__device__ __forceinline__ void split_f32(float v, __nv_bfloat16& hi, __nv_bfloat16& lo) {
    hi = __float2bfloat16(v);
    lo = __float2bfloat16(v - __bfloat162float(hi));
}
__device__ __forceinline__ void split_f32h(float v, __half& hi, __half& lo) {
    hi = __float2half(v);
    lo = __float2half(v - __half2float(hi));
}

// smem: BK=16 slabs, row stride 24 elems (48 B, conflict-free ldmatrix row phases)
#define SKP 24
#define SLAB_ELEMS (128 * SKP)   // 3072 elems = 6144 B
#define SLAB_BYTES (SLAB_ELEMS * 2)

// ---------------- bf16 3-pass NT GEMM core ------------------------------------------
// A fp32 (split on the fly). B either fp32 or pre-split bf16 (BPRE).
// 256 threads = 8 warps (2m x 4n), 64x32 per warp, K multiple of 16.
// R15 base; ONLY change: LDSM interleaved with MMA (prefetch mt+1 frags during mt's
// MMAs) to break the post-barrier LDSM-burst / MMA-burst alternation.
template <bool BPRE, class Epi>
__device__ __forceinline__ void gemm_core(
    const float* __restrict__ Af, int lda, int Mv,
    const float* __restrict__ Bf,
    const __nv_bfloat16* __restrict__ Bhi, const __nv_bfloat16* __restrict__ Blo,
    int ldb, int Nv, int K, Epi epi)
{
    __shared__ __align__(16) __nv_bfloat16 sm[2][4][SLAB_ELEMS];  // 49152 B
    const int tid  = threadIdx.x;
    const int wid  = tid >> 5, lane = tid & 31;
    const int g    = lane >> 2, tg = lane & 3;
    const int wm   = (wid >> 2) * 64;
    const int wn   = (wid & 3) * 32;
    const int lrow = lane & 15, lhalf = (lane >> 4) * 8;

    float C[4][4][4];
    #pragma unroll
    for (int i = 0; i < 4; i++)
        #pragma unroll
        for (int j = 0; j < 4; j++)
            #pragma unroll
            for (int k = 0; k < 4; k++) C[i][j][k] = 0.f;

    float4 ra[2], rbf[2];
    uint4  rbh, rbl;

    auto load_slab = [&](int s) {
        const int k0 = s << 4;
        #pragma unroll
        for (int it = 0; it < 2; it++) {
            int idx = tid + it * 256;
            int r = idx >> 2, q = idx & 3;
            ra[it] = (r < Mv) ? *(const float4*)(Af + (size_t)r * lda + k0 + q * 4)
                              : make_float4(0.f, 0.f, 0.f, 0.f);
        }
        if (!BPRE) {
            #pragma unroll
            for (int it = 0; it < 2; it++) {
                int idx = tid + it * 256;
                int r = idx >> 2, q = idx & 3;
                rbf[it] = (r < Nv) ? *(const float4*)(Bf + (size_t)r * ldb + k0 + q * 4)
                                   : make_float4(0.f, 0.f, 0.f, 0.f);
            }
        } else {
            int r = tid >> 1, q = tid & 1;
            if (r < Nv) {
                rbh = *(const uint4*)(Bhi + (size_t)r * ldb + k0 + q * 8);
                rbl = *(const uint4*)(Blo + (size_t)r * ldb + k0 + q * 8);
            } else {
                rbh = make_uint4(0u, 0u, 0u, 0u); rbl = rbh;
            }
        }
    };

    auto store_f4 = [&](__nv_bfloat16* hi, __nv_bfloat16* lo, int r, int q, float4 v) {
        __nv_bfloat16 h0, l0, h1, l1, h2, l2, h3, l3;
        split_f32(v.x, h0, l0); split_f32(v.y, h1, l1);
        split_f32(v.z, h2, l2); split_f32(v.w, h3, l3);
        int e = r * SKP + q * 4;
        *(__nv_bfloat162*)(hi + e)     = __halves2bfloat162(h0, h1);
        *(__nv_bfloat162*)(hi + e + 2) = __halves2bfloat162(h2, h3);
        *(__nv_bfloat162*)(lo + e)     = __halves2bfloat162(l0, l1);
        *(__nv_bfloat162*)(lo + e + 2) = __halves2bfloat162(l2, l3);
    };

    auto store_slab = [&](int buf) {
        #pragma unroll
        for (int it = 0; it < 2; it++) {
            int idx = tid + it * 256;
            store_f4(sm[buf][0], sm[buf][1], idx >> 2, idx & 3, ra[it]);
        }
        if (!BPRE) {
            #pragma unroll
            for (int it = 0; it < 2; it++) {
                int idx = tid + it * 256;
                store_f4(sm[buf][2], sm[buf][3], idx >> 2, idx & 3, rbf[it]);
            }
        } else {
            int r = tid >> 1, q = tid & 1;
            *(uint4*)(&sm[buf][2][r * SKP + q * 8]) = rbh;
            *(uint4*)(&sm[buf][3][r * SKP + q * 8]) = rbl;
        }
    };

    const int slabs = K >> 4;
    load_slab(0);
    store_slab(0);
    __syncthreads();

    for (int s = 0; s < slabs; s++) {
        const bool more = (s + 1 < slabs);
        if (more) load_slab(s + 1);

        const uint32_t sbase = smem_u32(&sm[s & 1][0][0]);
        uint32_t ah[4][4], al[4][4], bfr[2][4], blr[2][4];
        // B frags + first A tile only; remaining A tiles prefetched under MMAs
        #pragma unroll
        for (int np = 0; np < 2; np++) {
            uint32_t off = (uint32_t)((wn + np * 16 + lrow) * SKP + lhalf) * 2u;
            ldsm4(bfr[np], sbase + 2 * SLAB_BYTES + off);
            ldsm4(blr[np], sbase + 3 * SLAB_BYTES + off);
        }
        {
            uint32_t off = (uint32_t)((wm + lrow) * SKP + lhalf) * 2u;
            ldsm4(ah[0], sbase + off);
            ldsm4(al[0], sbase + SLAB_BYTES + off);
        }
        #pragma unroll
        for (int mt = 0; mt < 4; mt++) {
            if (mt < 3) {   // prefetch next A tile; hides under this tile's 12 MMAs
                uint32_t off = (uint32_t)((wm + (mt + 1) * 16 + lrow) * SKP + lhalf) * 2u;
                ldsm4(ah[mt + 1], sbase + off);
                ldsm4(al[mt + 1], sbase + SLAB_BYTES + off);
            }
            #pragma unroll
            for (int nt = 0; nt < 4; nt++) {
                int np = nt >> 1, lo = nt & 1;
                uint32_t bh[2] = { bfr[np][lo], bfr[np][lo + 2] };
                uint32_t bl[2] = { blr[np][lo], blr[np][lo + 2] };
                mma16816(C[mt][nt], ah[mt], bh);   // hi*hi
                mma16816(C[mt][nt], ah[mt], bl);   // hi*lo
                mma16816(C[mt][nt], al[mt], bh);   // lo*hi
            }
        }

        if (more) store_slab((s + 1) & 1);
        __syncthreads();
    }

    #pragma unroll
    for (int mt = 0; mt < 4; mt++)
        #pragma unroll
        for (int nt = 0; nt < 4; nt++)
            epi(wm + mt * 16 + g, wn + nt * 8 + 2 * tg, C[mt][nt]);
}

// ---------------- fp16 2-pass NT GEMM core for out = P Z ---------------------------
// A = plain fp16 P [128 x K]. B = fp16 (hi, lo). Same 8-warp layout, same interleave.
template <class Epi>
__device__ __forceinline__ void gemm_core_pz(
    const __half* __restrict__ A, int lda,
    const __half* __restrict__ Bhi, const __half* __restrict__ Blo, int ldb,
    int K, Epi epi)
{
    __shared__ __align__(16) __half sm2[2][3][SLAB_ELEMS];   // 36864 B
    const int tid  = threadIdx.x;
    const int wid  = tid >> 5, lane = tid & 31;
    const int g    = lane >> 2, tg = lane & 3;
    const int wm   = (wid >> 2) * 64;
    const int wn   = (wid & 3) * 32;
    const int lrow = lane & 15, lhalf = (lane >> 4) * 8;
    const int cr   = tid >> 1, cq = tid & 1;

    float C[4][4][4];
    #pragma unroll
    for (int i = 0; i < 4; i++)
        #pragma unroll
        for (int j = 0; j < 4; j++)
            #pragma unroll
            for (int k = 0; k < 4; k++) C[i][j][k] = 0.f;

    uint4 rA, rbh, rbl;
    auto load_slab = [&](int s) {
        const int k0 = s << 4;
        rA  = *(const uint4*)(A   + (size_t)cr * lda + k0 + cq * 8);
        rbh = *(const uint4*)(Bhi + (size_t)cr * ldb + k0 + cq * 8);
        rbl = *(const uint4*)(Blo + (size_t)cr * ldb + k0 + cq * 8);
    };
    auto store_slab = [&](int buf) {
        int e = cr * SKP + cq * 8;
        *(uint4*)(&sm2[buf][0][e]) = rA;
        *(uint4*)(&sm2[buf][1][e]) = rbh;
        *(uint4*)(&sm2[buf][2][e]) = rbl;
    };

    const int slabs = K >> 4;
    load_slab(0);
    store_slab(0);
    __syncthreads();

    for (int s = 0; s < slabs; s++) {
        const bool more = (s + 1 < slabs);
        if (more) load_slab(s + 1);

        const uint32_t sbase = smem_u32(&sm2[s & 1][0][0]);
        uint32_t ah[4][4], bfr[2][4], blr[2][4];
        #pragma unroll
        for (int np = 0; np < 2; np++) {
            uint32_t off = (uint32_t)((wn + np * 16 + lrow) * SKP + lhalf) * 2u;
            ldsm4(bfr[np], sbase + (uint32_t)SLAB_BYTES + off);
            ldsm4(blr[np], sbase + 2u * SLAB_BYTES + off);
        }
        {
            uint32_t off = (uint32_t)((wm + lrow) * SKP + lhalf) * 2u;
            ldsm4(ah[0], sbase + off);
        }
        #pragma unroll
        for (int mt = 0; mt < 4; mt++) {
            if (mt < 3) {
                uint32_t off = (uint32_t)((wm + (mt + 1) * 16 + lrow) * SKP + lhalf) * 2u;
                ldsm4(ah[mt + 1], sbase + off);
            }
            #pragma unroll
            for (int nt = 0; nt < 4; nt++) {
                int np = nt >> 1, lo = nt & 1;
                uint32_t bh[2] = { bfr[np][lo], bfr[np][lo + 2] };
                uint32_t bl[2] = { blr[np][lo], blr[np][lo + 2] };
                mma16816h(C[mt][nt], ah[mt], bh);   // P * Z_hi
                mma16816h(C[mt][nt], ah[mt], bl);   // P * Z_lo
            }
        }

        if (more) store_slab((s + 1) & 1);
        __syncthreads();
    }

    #pragma unroll
    for (int mt = 0; mt < 4; mt++)
        #pragma unroll
        for (int nt = 0; nt < 4; nt++)
            epi(wm + mt * 16 + g, wn + nt * 8 + 2 * tg, C[mt][nt]);
}

// ---------------- offsets (int32/int64 lengths) ----------------
__global__ void offsets_kernel(const int* __restrict__ lens_raw, int count, int ntok) {
    if (threadIdx.x != 0 || blockIdx.x != 0) return;
    bool is64 = (count >= 2) && (lens_raw[1] == 0) && (lens_raw[0] != 0);
    int acc = 0;
    for (int i = 0; i < BMAX; i++) {
        int L = 0;
        if (i < count && acc < ntok) L = lens_raw[is64 ? 2 * i : i];
        if (L < 0) L = 0;
        if (L > LMAX) L = LMAX;
        g_len[i] = L; g_off[i] = acc; acc += L;
    }
}

// ---------------- transpose + fp16 split: h[N,512] -> zT[512, NTOK_MAX] -------------
__global__ void transpose_split(const float* __restrict__ h, int Ntok) {
    __shared__ float t[32][33];
    int d0 = blockIdx.x * 32, n0 = blockIdx.y * 32;
    for (int i = threadIdx.y; i < 32; i += 8) {
        int n = n0 + i;
        t[i][threadIdx.x] = (n < Ntok) ? h[(size_t)n * DFIX + d0 + threadIdx.x] : 0.f;
    }
    __syncthreads();
    for (int i = threadIdx.y; i < 32; i += 8) {
        int d = d0 + i, n = n0 + threadIdx.x;
        if (n >= NTOK_MAX) continue;
        float v = t[threadIdx.x][i];
        __half hi, lo; split_f32h(v, hi, lo);
        g_zThi[(size_t)d * NTOK_MAX + n] = hi;
        g_zTlo[(size_t)d * NTOK_MAX + n] = lo;
    }
}

// ---------------- GEMM 1: x = h W^T + b ----------------
__global__ __launch_bounds__(256)
void linear_gemm(const float* __restrict__ h, const float* __restrict__ W,
                 const float* __restrict__ bias, int Ntok)
{
    int col0 = blockIdx.x * 128, row0 = blockIdx.y * 128;
    if (row0 >= Ntok) return;
    int Mv = Ntok - row0; if (Mv > 128) Mv = 128;
    auto epi = [&](int gm, int gn, const float* c) {
        int gcol = col0 + gn;
        float b0 = bias[gcol], b1 = bias[gcol + 1];
        #pragma unroll
        for (int half = 0; half < 2; half++) {
            int grow = row0 + gm + half * 8;
            if (grow >= Ntok) continue;
            *(float2*)(g_x + (size_t)grow * DFIX + gcol) =
                make_float2(c[half * 2] + b0, c[half * 2 + 1] + b1);
        }
    };
    gemm_core<false>(h + (size_t)row0 * DFIX, DFIX, Mv,
                     W + (size_t)col0 * DFIX, nullptr, nullptr, DFIX, 128,
                     DFIX, epi);
}

// ---------------- GEMM 2: S = Z Y^T per segment ----------------
__global__ __launch_bounds__(256)
void scores_gemm(const float* __restrict__ h)
{
    int b = blockIdx.z;
    int L = g_len[b];
    int col0 = blockIdx.x * 128, row0 = blockIdx.y * 128;
    if (L == 0 || row0 >= L || col0 >= L) return;
    int off = g_off[b];
    int Mv = L - row0; if (Mv > 128) Mv = 128;
    int Nv = L - col0; if (Nv > 128) Nv = 128;
    float* S = g_S + (size_t)b * LMAX * LMAX;
    auto epi = [&](int gm, int gn, const float* c) {
        if (gn >= Nv) return;
        #pragma unroll
        for (int half = 0; half < 2; half++) {
            int rm = gm + half * 8;
            if (rm >= Mv) continue;
            *(float2*)(S + (size_t)(row0 + rm) * LMAX + col0 + gn) =
                make_float2(c[half * 2], c[half * 2 + 1]);
        }
    };
    gemm_core<false>(h + (size_t)(off + row0) * DFIX, DFIX, Mv,
                     g_x + (size_t)(off + col0) * DFIX, nullptr, nullptr, DFIX, Nv,
                     DFIX, epi);
}

// ---------------- softmax: fp32 row in, fp16 P[L] out in place at row start --------
__global__ void softmax_kernel()
{
    int b = blockIdx.y, l = blockIdx.x;
    int L = g_len[b];
    if (l >= L) return;
    float* row = g_S + (size_t)b * LMAX * LMAX + (size_t)l * LMAX;
    __half* P = (__half*)row;
    int tid = threadIdx.x;

    float v[LMAX / 256];
    float mx = -1e30f;
    #pragma unroll
    for (int i = 0; i < LMAX / 256; i++) {
        int m = tid + i * 256;
        v[i] = (m < L) ? row[m] : -1e30f;
        mx = fmaxf(mx, v[i]);
    }
    __shared__ float red[256];
    red[tid] = mx; __syncthreads();
    #pragma unroll
    for (int s = 128; s > 0; s >>= 1) {
        if (tid < s) red[tid] = fmaxf(red[tid], red[tid + s]);
        __syncthreads();
    }
    mx = red[0]; __syncthreads();

    float sum = 0.f;
    #pragma unroll
    for (int i = 0; i < LMAX / 256; i++) {
        int m = tid + i * 256;
        v[i] = (m < L) ? __expf(v[i] - mx) : 0.f;
        sum += v[i];
    }
    red[tid] = sum; __syncthreads();
    #pragma unroll
    for (int s = 128; s > 0; s >>= 1) {
        if (tid < s) red[tid] += red[tid + s];
        __syncthreads();
    }
    float inv = 1.f / red[0];
    __syncthreads();   // all fp32 reads of this row precede the in-place overwrite

    #pragma unroll
    for (int i = 0; i < LMAX / 256; i++) {
        int m = tid + i * 256;
        if (m < L) P[m] = __float2half(v[i] * inv);
    }
}

// ---------------- GEMM 3: out = P Z  (fp16 2-pass core) ----------------
__global__ __launch_bounds__(256)
void out_gemm(float* __restrict__ out)
{
    int b = blockIdx.z;
    int L = g_len[b];
    int col0 = blockIdx.x * 128, row0 = blockIdx.y * 128;
    if (L == 0 || row0 >= L) return;
    int off = g_off[b];
    int Mv = L - row0; if (Mv > 128) Mv = 128;
    const __half* P = (const __half*)(g_S + (size_t)b * LMAX * LMAX)
                      + (size_t)row0 * 2 * LMAX;   // row stride 2*LMAX halves
    auto epi = [&](int gm, int gn, const float* c) {
        #pragma unroll
        for (int half = 0; half < 2; half++) {
            int rm = gm + half * 8;
            if (rm >= Mv) continue;
            *(float2*)(out + (size_t)(off + row0 + rm) * DFIX + col0 + gn) =
                make_float2(c[half * 2], c[half * 2 + 1]);
        }
    };
    gemm_core_pz(P, 2 * LMAX,
                 g_zThi + (size_t)col0 * NTOK_MAX + off,
                 g_zTlo + (size_t)col0 * NTOK_MAX + off, NTOK_MAX,
                 L /* K: multiple of 64 */, epi);
}

// ---------------- launch (NO device symbols passed as args — host shadows!) --------
extern "C" void kernel_launch(void* const* d_in, const int* in_sizes, int n_in,
                              void* d_out, int out_size)
{
    const float* h    = (const float*)d_in[0];
    const float* W    = (const float*)d_in[1];
    const float* bias = (const float*)d_in[2];
    const int*   lens = (const int*)d_in[3];

    int D    = in_sizes[2];
    int Ntok = in_sizes[0] / D;
    int B    = in_sizes[3];
    if (B > BMAX) B = BMAX;
    int Bz = B < SEGMAX ? B : SEGMAX;

    offsets_kernel<<<1, 32>>>(lens, B, Ntok);

    transpose_split<<<dim3(DFIX / 32, (Ntok + 31) / 32), dim3(32, 8)>>>(h, Ntok);

    int rowTiles = (Ntok + 127) / 128;
    linear_gemm<<<dim3(DFIX / 128, rowTiles), 256>>>(h, W, bias, Ntok);

    scores_gemm<<<dim3(LMAX / 128, LMAX / 128, Bz), 256>>>(h);

    softmax_kernel<<<dim3(LMAX, Bz), 256>>>();

    out_gemm<<<dim3(DFIX / 128, LMAX / 128, Bz), 256>>>((float*)d_out);
}